// round 2
// baseline (speedup 1.0000x reference)
#include <cuda_runtime.h>
#include <cuda_bf16.h>
#include <cstdint>

#define T_STEPS 500
#define BATCH   512
#define CIN     128
#define NHID    512
#define GBLKS   128           // persistent blocks; slice = NHID/GBLKS = 4 neurons
#define PTHREADS 256

// ---------------- static device scratch (no allocations allowed) ----------------
__device__ float g_xtr[(size_t)T_STEPS * BATCH * CIN];        // [(t*B+b)][c]
__device__ float g_in1[(size_t)T_STEPS * BATCH * NHID];       // x@W1^T + b1 + br2
__device__ float g_W1T[CIN * NHID];                           // [c][n]
__device__ unsigned g_ms1[3][BATCH * 16];                     // s1 masks (triple buf)
__device__ unsigned g_ms2[4][BATCH * 16];                     // s2 masks (quad buf)
__device__ unsigned g_ctr;                                    // grid barrier counter

// ---------------- init: zero masks + barrier counter ----------------------------
__global__ void k_init() {
    int idx = blockIdx.x * blockDim.x + threadIdx.x;
    int stride = gridDim.x * blockDim.x;
    const int n1 = 3 * BATCH * 16, n2 = 4 * BATCH * 16;
    unsigned* m1 = &g_ms1[0][0];
    unsigned* m2 = &g_ms2[0][0];
    for (int i = idx; i < n1; i += stride) m1[i] = 0u;
    for (int i = idx; i < n2; i += stride) m2[i] = 0u;
    if (idx == 0) g_ctr = 0u;
}

// ---------------- x[b][c][t] -> g_xtr[(t*B+b)][c] -------------------------------
__global__ void k_transpose_x(const float* __restrict__ x) {
    __shared__ float tile[32][33];
    int b = blockIdx.z;
    int t0 = blockIdx.x * 32, c0 = blockIdx.y * 32;
    int tx = threadIdx.x, ty = threadIdx.y;
#pragma unroll
    for (int i = 0; i < 32; i += 8) {
        int c = c0 + ty + i, t = t0 + tx;
        if (t < T_STEPS && c < CIN)
            tile[ty + i][tx] = x[((size_t)b * CIN + c) * T_STEPS + t];
    }
    __syncthreads();
#pragma unroll
    for (int i = 0; i < 32; i += 8) {
        int t = t0 + ty + i, c = c0 + tx;
        if (t < T_STEPS && c < CIN)
            g_xtr[((size_t)t * BATCH + b) * CIN + c] = tile[tx][ty + i];
    }
}

// ---------------- W1[n][c] -> g_W1T[c][n] ----------------------------------------
__global__ void k_transpose_w1(const float* __restrict__ W1) {
    __shared__ float tile[32][33];
    int c0 = blockIdx.x * 32, n0 = blockIdx.y * 32;
    int tx = threadIdx.x, ty = threadIdx.y;
#pragma unroll
    for (int i = 0; i < 32; i += 8) {
        int n = n0 + ty + i, c = c0 + tx;
        if (n < NHID && c < CIN) tile[ty + i][tx] = W1[(size_t)n * CIN + c];
    }
    __syncthreads();
#pragma unroll
    for (int i = 0; i < 32; i += 8) {
        int c = c0 + ty + i, n = n0 + tx;
        if (n < NHID && c < CIN) g_W1T[(size_t)c * NHID + n] = tile[tx][ty + i];
    }
}

// ---------------- in1 = xtr @ W1T + (b1 + br2); M=256000, K=128, N=512 -----------
__global__ __launch_bounds__(256)
void k_gemm_in1(const float* __restrict__ b1, const float* __restrict__ br2) {
    __shared__ float As[32][129];
    __shared__ float Bs[32][64];
    const float* A = g_xtr;
    const float* B = g_W1T;
    int bm = blockIdx.x * 128, bn = blockIdx.y * 64;
    int tid = threadIdx.x;
    int tx = tid & 15, ty = tid >> 4;
    int arow = tid >> 3, acol = (tid & 7) * 4;
    int brow = tid >> 4, bcol = (tid & 15) * 4;

    float acc[8][4];
#pragma unroll
    for (int i = 0; i < 8; i++)
#pragma unroll
        for (int j = 0; j < 4; j++) acc[i][j] = 0.0f;

    for (int k0 = 0; k0 < CIN; k0 += 32) {
#pragma unroll
        for (int i = 0; i < 4; i++) {
            float4 v = *(const float4*)(A + (size_t)(bm + arow + 32 * i) * CIN + k0 + acol);
            As[acol + 0][arow + 32 * i] = v.x;
            As[acol + 1][arow + 32 * i] = v.y;
            As[acol + 2][arow + 32 * i] = v.z;
            As[acol + 3][arow + 32 * i] = v.w;
        }
#pragma unroll
        for (int i = 0; i < 2; i++) {
            *(float4*)&Bs[brow + 16 * i][bcol] =
                *(const float4*)(B + (size_t)(k0 + brow + 16 * i) * NHID + bn + bcol);
        }
        __syncthreads();
#pragma unroll
        for (int k = 0; k < 32; k++) {
            float a[8];
#pragma unroll
            for (int i = 0; i < 8; i++) a[i] = As[k][ty * 8 + i];
            float4 bv = *(const float4*)&Bs[k][tx * 4];
#pragma unroll
            for (int i = 0; i < 8; i++) {
                acc[i][0] += a[i] * bv.x;
                acc[i][1] += a[i] * bv.y;
                acc[i][2] += a[i] * bv.z;
                acc[i][3] += a[i] * bv.w;
            }
        }
        __syncthreads();
    }
    int col = bn + tx * 4;
    float bb0 = b1[col + 0] + br2[col + 0];
    float bb1 = b1[col + 1] + br2[col + 1];
    float bb2 = b1[col + 2] + br2[col + 2];
    float bb3 = b1[col + 3] + br2[col + 3];
#pragma unroll
    for (int i = 0; i < 8; i++) {
        size_t row = (size_t)(bm + ty * 8 + i);
        float4 o;
        o.x = acc[i][0] + bb0;
        o.y = acc[i][1] + bb1;
        o.z = acc[i][2] + bb2;
        o.w = acc[i][3] + bb3;
        *(float4*)(g_in1 + row * NHID + bn + tx * 4) = o;
    }
}

// ---------------- mask helpers ---------------------------------------------------
__device__ __forceinline__ void load_mask16(const unsigned* __restrict__ row, unsigned mw[16]) {
    uint4 q0 = __ldcg((const uint4*)(row + 0));
    uint4 q1 = __ldcg((const uint4*)(row + 4));
    uint4 q2 = __ldcg((const uint4*)(row + 8));
    uint4 q3 = __ldcg((const uint4*)(row + 12));
    mw[0] = q0.x; mw[1] = q0.y; mw[2] = q0.z; mw[3] = q0.w;
    mw[4] = q1.x; mw[5] = q1.y; mw[6] = q1.z; mw[7] = q1.w;
    mw[8] = q2.x; mw[9] = q2.y; mw[10] = q2.z; mw[11] = q2.w;
    mw[12] = q3.x; mw[13] = q3.y; mw[14] = q3.z; mw[15] = q3.w;
}

// accumulate one weight table over mask bits
__device__ __forceinline__ float4 accum1(const unsigned* __restrict__ row,
                                         const float4* __restrict__ Wsh) {
    unsigned mw[16];
    load_mask16(row, mw);
    float4 a = make_float4(0.f, 0.f, 0.f, 0.f);
#pragma unroll
    for (int w = 0; w < 16; w++) {
        unsigned m = mw[w];
        const float4* base = Wsh + (w << 5);
        while (m) {
            int b = __ffs(m) - 1;
            m &= m - 1u;
            float4 wv = base[b];
            a.x += wv.x; a.y += wv.y; a.z += wv.z; a.w += wv.w;
        }
    }
    return a;
}

// accumulate two weight tables over the same mask
__device__ __forceinline__ void accum2(const unsigned* __restrict__ row,
                                       const float4* __restrict__ WshA,
                                       const float4* __restrict__ WshB,
                                       float4& aA, float4& aB) {
    unsigned mw[16];
    load_mask16(row, mw);
#pragma unroll
    for (int w = 0; w < 16; w++) {
        unsigned m = mw[w];
        int off = w << 5;
        while (m) {
            int b = __ffs(m) - 1;
            m &= m - 1u;
            float4 wa = WshA[off + b];
            float4 wb = WshB[off + b];
            aA.x += wa.x; aA.y += wa.y; aA.z += wa.z; aA.w += wa.w;
            aB.x += wb.x; aB.y += wb.y; aB.z += wb.z; aB.w += wb.w;
        }
    }
}

struct LayerState {
    float4 mem, sprev, cnt;
};

// ---------------- persistent recurrent kernel ------------------------------------
__global__ __launch_bounds__(PTHREADS, 1)
void k_rsnn(const float* __restrict__ Wr2, const float* __restrict__ W2,
            const float* __restrict__ W4,
            const float* __restrict__ b2, const float* __restrict__ br2,
            const float* __restrict__ b4,
            const float* __restrict__ Vth1, const float* __restrict__ tau1,
            const float* __restrict__ Vth2, const float* __restrict__ tau2,
            const float* __restrict__ tau_out,
            float* __restrict__ out) {
    __shared__ float4 Wr2sh[NHID];   // [j] -> Wr2[n0..n0+3][j]
    __shared__ float4 W2sh[NHID];
    __shared__ float2 W4sh[NHID];    // [j] -> W4[0][j], W4[1][j]

    const int tid = threadIdx.x;
    const int g = blockIdx.x;
    const int n0 = g * 4;
    const int word = n0 >> 5;
    const int shift = n0 & 31;

    for (int i = tid; i < NHID; i += PTHREADS) {
        Wr2sh[i] = make_float4(Wr2[(size_t)(n0 + 0) * NHID + i], Wr2[(size_t)(n0 + 1) * NHID + i],
                               Wr2[(size_t)(n0 + 2) * NHID + i], Wr2[(size_t)(n0 + 3) * NHID + i]);
        W2sh[i] = make_float4(W2[(size_t)(n0 + 0) * NHID + i], W2[(size_t)(n0 + 1) * NHID + i],
                              W2[(size_t)(n0 + 2) * NHID + i], W2[(size_t)(n0 + 3) * NHID + i]);
        W4sh[i] = make_float2(W4[i], W4[NHID + i]);
    }
    __syncthreads();

    const float4 t1v = *(const float4*)(tau1 + n0);
    const float4 v1v = *(const float4*)(Vth1 + n0);
    const float4 t2v = *(const float4*)(tau2 + n0);
    const float4 v2v = *(const float4*)(Vth2 + n0);
    float4 bias2;
    bias2.x = b2[n0 + 0] + br2[n0 + 0];
    bias2.y = b2[n0 + 1] + br2[n0 + 1];
    bias2.z = b2[n0 + 2] + br2[n0 + 2];
    bias2.w = b2[n0 + 3] + br2[n0 + 3];

    const int rA = tid;          // batch rows owned by this thread
    const int rB = tid + PTHREADS;

    LayerState l1a, l1b, l2a, l2b;
    const float4 z4 = make_float4(0.f, 0.f, 0.f, 0.f);
    l1a.mem = l1a.sprev = l1a.cnt = z4;
    l1b.mem = l1b.sprev = l1b.cnt = z4;
    l2a.mem = l2a.sprev = l2a.cnt = z4;
    l2b.mem = l2b.sprev = l2b.cnt = z4;

    // readout state (threads 0..3 own rows g*4 + tid)
    float memo_x = 0.f, memo_y = 0.f;
    const int rowR = g * 4 + tid;
    const float to0 = tau_out[0], to1 = tau_out[1];
    const float b40 = b4[0], b41 = b4[1];

    volatile unsigned* ctr_v = (volatile unsigned*)&g_ctr;

    for (int p = 0; p < T_STEPS + 2; p++) {
        const unsigned* ms1_rd = g_ms1[(p + 2) % 3];   // s1[p-1]
        unsigned* ms1_wr = g_ms1[p % 3];               // s1[p]
        const unsigned* ms2_rd = g_ms2[(p + 2) % 4];   // s2[p-2]
        unsigned* ms2_wr = g_ms2[(p + 3) % 4];         // s2[p-1]

        const bool do_l1 = (p <= T_STEPS - 1);
        const bool do_l2 = (p >= 1 && p <= T_STEPS);

        if (p <= T_STEPS) {
#pragma unroll
            for (int half = 0; half < 2; half++) {
                const int r = half ? rB : rA;
                LayerState& s1 = half ? l1b : l1a;
                LayerState& s2 = half ? l2b : l2a;

                // one pass over s1[p-1] mask feeds layer1-rec and layer2-ff
                float4 a_rec1 = z4, a_ff2 = z4;
                accum2(ms1_rd + r * 16, Wr2sh, W2sh, a_rec1, a_ff2);

                if (do_l1) {
                    float4 i1 = *(const float4*)(g_in1 + (((size_t)p * BATCH + r) << 9) + n0);
                    i1.x += a_rec1.x; i1.y += a_rec1.y; i1.z += a_rec1.z; i1.w += a_rec1.w;
                    s1.mem.x = t1v.x * s1.mem.x * (1.f - s1.sprev.x) + i1.x;
                    s1.mem.y = t1v.y * s1.mem.y * (1.f - s1.sprev.y) + i1.y;
                    s1.mem.z = t1v.z * s1.mem.z * (1.f - s1.sprev.z) + i1.z;
                    s1.mem.w = t1v.w * s1.mem.w * (1.f - s1.sprev.w) + i1.w;
                    float sx = (s1.mem.x > v1v.x) ? 1.f : 0.f;
                    float sy = (s1.mem.y > v1v.y) ? 1.f : 0.f;
                    float sz = (s1.mem.z > v1v.z) ? 1.f : 0.f;
                    float sw = (s1.mem.w > v1v.w) ? 1.f : 0.f;
                    s1.sprev = make_float4(sx, sy, sz, sw);
                    s1.cnt.x += sx; s1.cnt.y += sy; s1.cnt.z += sz; s1.cnt.w += sw;
                    unsigned nib = (sx > 0.f ? 1u : 0u) | (sy > 0.f ? 2u : 0u) |
                                   (sz > 0.f ? 4u : 0u) | (sw > 0.f ? 8u : 0u);
                    if (nib) atomicOr(ms1_wr + r * 16 + word, nib << shift);
                }
                if (do_l2) {
                    float4 a_rec2 = accum1(ms2_rd + r * 16, Wr2sh);
                    float4 i2;
                    i2.x = a_ff2.x + a_rec2.x + bias2.x;
                    i2.y = a_ff2.y + a_rec2.y + bias2.y;
                    i2.z = a_ff2.z + a_rec2.z + bias2.z;
                    i2.w = a_ff2.w + a_rec2.w + bias2.w;
                    s2.mem.x = t2v.x * s2.mem.x * (1.f - s2.sprev.x) + i2.x;
                    s2.mem.y = t2v.y * s2.mem.y * (1.f - s2.sprev.y) + i2.y;
                    s2.mem.z = t2v.z * s2.mem.z * (1.f - s2.sprev.z) + i2.z;
                    s2.mem.w = t2v.w * s2.mem.w * (1.f - s2.sprev.w) + i2.w;
                    float sx = (s2.mem.x > v2v.x) ? 1.f : 0.f;
                    float sy = (s2.mem.y > v2v.y) ? 1.f : 0.f;
                    float sz = (s2.mem.z > v2v.z) ? 1.f : 0.f;
                    float sw = (s2.mem.w > v2v.w) ? 1.f : 0.f;
                    s2.sprev = make_float4(sx, sy, sz, sw);
                    s2.cnt.x += sx; s2.cnt.y += sy; s2.cnt.z += sz; s2.cnt.w += sw;
                    unsigned nib = (sx > 0.f ? 1u : 0u) | (sy > 0.f ? 2u : 0u) |
                                   (sz > 0.f ? 4u : 0u) | (sw > 0.f ? 8u : 0u);
                    if (nib) atomicOr(ms2_wr + r * 16 + word, nib << shift);
                }
            }
        }

        // readout for step t = p-2 (reads s2[p-2] masks)
        if (p >= 2 && tid < 4) {
            unsigned mw[16];
            load_mask16(ms2_rd + rowR * 16, mw);
            float ax = 0.f, ay = 0.f;
#pragma unroll
            for (int w = 0; w < 16; w++) {
                unsigned m = mw[w];
                int off = w << 5;
                while (m) {
                    int b = __ffs(m) - 1;
                    m &= m - 1u;
                    float2 wv = W4sh[off + b];
                    ax += wv.x; ay += wv.y;
                }
            }
            memo_x = to0 * memo_x + ax + b40;
            memo_y = to1 * memo_y + ay + b41;
            int t = p - 2;
            out[(size_t)rowR * (2 * T_STEPS) + t] = memo_x;
            out[(size_t)rowR * (2 * T_STEPS) + T_STEPS + t] = memo_y;
        }

        // clear mask buffers for step p+1 (nobody reads/writes those this phase)
        {
            unsigned* c1 = g_ms1[(p + 1) % 3];
            unsigned* c2 = g_ms2[(p + 1) % 4];
            int idx = g * PTHREADS + tid;   // 0..32767
            if (idx < BATCH * 16) c1[idx] = 0u;
            else if (idx < 2 * BATCH * 16) c2[idx - BATCH * 16] = 0u;
        }

        // grid barrier
        __syncthreads();
        __threadfence();
        if (tid == 0) {
            atomicAdd(&g_ctr, 1u);
            unsigned target = (unsigned)(p + 1) * (unsigned)gridDim.x;
            while (*ctr_v < target) __nanosleep(64);
        }
        __syncthreads();
    }

    // spike-count outputs: sc1 at offset B*2*T, sc2 after it
    const float inv = 1.f / (float)T_STEPS;
    float* sc1 = out + (size_t)BATCH * 2 * T_STEPS;
    float* sc2 = sc1 + (size_t)BATCH * NHID;
    float4 o;
    o = make_float4(l1a.cnt.x * inv, l1a.cnt.y * inv, l1a.cnt.z * inv, l1a.cnt.w * inv);
    *(float4*)(sc1 + (size_t)rA * NHID + n0) = o;
    o = make_float4(l1b.cnt.x * inv, l1b.cnt.y * inv, l1b.cnt.z * inv, l1b.cnt.w * inv);
    *(float4*)(sc1 + (size_t)rB * NHID + n0) = o;
    o = make_float4(l2a.cnt.x * inv, l2a.cnt.y * inv, l2a.cnt.z * inv, l2a.cnt.w * inv);
    *(float4*)(sc2 + (size_t)rA * NHID + n0) = o;
    o = make_float4(l2b.cnt.x * inv, l2b.cnt.y * inv, l2b.cnt.z * inv, l2b.cnt.w * inv);
    *(float4*)(sc2 + (size_t)rB * NHID + n0) = o;
}

// ---------------- launch ----------------------------------------------------------
extern "C" void kernel_launch(void* const* d_in, const int* in_sizes, int n_in,
                              void* d_out, int out_size) {
    (void)in_sizes; (void)n_in; (void)out_size;
    const float* x    = (const float*)d_in[0];
    const float* W1   = (const float*)d_in[1];
    const float* b1   = (const float*)d_in[2];
    const float* W2   = (const float*)d_in[3];
    const float* b2   = (const float*)d_in[4];
    const float* Wr2  = (const float*)d_in[5];
    const float* br2  = (const float*)d_in[6];
    // d_in[7..10]: W3, b3, Wr3, br3 — provably dead (layer 3 never reaches outputs)
    const float* W4   = (const float*)d_in[11];
    const float* b4   = (const float*)d_in[12];
    const float* Vth1 = (const float*)d_in[13];
    const float* tau1 = (const float*)d_in[14];
    const float* Vth2 = (const float*)d_in[15];
    const float* tau2 = (const float*)d_in[16];
    // d_in[17..18]: Vth3, tau3 — dead
    const float* tau_out = (const float*)d_in[19];
    float* out = (float*)d_out;

    k_init<<<64, 256>>>();
    k_transpose_x<<<dim3((T_STEPS + 31) / 32, CIN / 32, BATCH), dim3(32, 8)>>>(x);
    k_transpose_w1<<<dim3(CIN / 32, NHID / 32), dim3(32, 8)>>>(W1);
    k_gemm_in1<<<dim3((T_STEPS * BATCH) / 128, NHID / 64), 256>>>(b1, br2);
    k_rsnn<<<GBLKS, PTHREADS>>>(Wr2, W2, W4, b2, br2, b4,
                                Vth1, tau1, Vth2, tau2, tau_out, out);
}